// round 15
// baseline (speedup 1.0000x reference)
#include <cuda_runtime.h>
#include <cuda_bf16.h>
#include <mma.h>
#include <math.h>
#include <cstdint>

using namespace nvcuda;

#define Bdim 16
#define Ldim 2048
#define Hdim 512
#define Ndim 32
#define HN   (Hdim*Ndim)
#define BH   (Bdim*Hdim)
#define BHL  (Bdim*Hdim*Ldim)

typedef unsigned long long u64;

// ---------------- scratch (device globals; no allocation allowed) -----------
__device__ float g_u [BHL];                  // (B,H,L) masked+LN'd input
__device__ float g_yf[BHL];                  // (B,H,L) fwd conv + D*u
__device__ float g_yb[BHL];                  // (B,H,L) bwd conv
__device__ __nv_bfloat16 g_yh[BHL];          // (B,L,H) gelu(y) hi
__device__ __nv_bfloat16 g_yl[BHL];          // (B,L,H) gelu(y) lo
__device__ __nv_bfloat16 g_wh[2*Hdim*Hdim];  // W hi (1024,512) K-major
__device__ __nv_bfloat16 g_wl[2*Hdim*Hdim];  // W lo
__device__ float g_dAr[HN], g_dAi[HN];
__device__ float g_c0r[HN], g_c0i[HN], g_c1r[HN], g_c1i[HN];
__device__ float g_len[Bdim];

// ---------------- packed f32x2 helpers (sm_100+) -----------------------------
__device__ __forceinline__ u64 pk2f(float a, float b) {
    u64 r; asm("mov.b64 %0,{%1,%2};" : "=l"(r) : "f"(a), "f"(b)); return r;
}
__device__ __forceinline__ u64 fma2(u64 a, u64 b, u64 c) {
    u64 d; asm("fma.rn.f32x2 %0,%1,%2,%3;" : "=l"(d) : "l"(a), "l"(b), "l"(c)); return d;
}
__device__ __forceinline__ u64 mul2(u64 a, u64 b) {
    u64 d; asm("mul.rn.f32x2 %0,%1,%2;" : "=l"(d) : "l"(a), "l"(b)); return d;
}
__device__ __forceinline__ float2 upk2(u64 v) {
    float2 f; asm("mov.b64 {%0,%1},%2;" : "=f"(f.x), "=f"(f.y) : "l"(v)); return f;
}

// ---------------- cp.async helpers -------------------------------------------
__device__ __forceinline__ uint32_t smem_u32(const void* p) {
    uint32_t a;
    asm("{ .reg .u64 t; cvta.to.shared.u64 t, %1; cvt.u32.u64 %0, t; }"
        : "=r"(a) : "l"(p));
    return a;
}
__device__ __forceinline__ void cpa16(uint32_t s, const void* g) {
    asm volatile("cp.async.cg.shared.global [%0], [%1], 16;" :: "r"(s), "l"(g));
}
#define CPA_COMMIT()  asm volatile("cp.async.commit_group;" ::: "memory")
#define CPA_WAIT(n)   asm volatile("cp.async.wait_group %0;" :: "n"(n) : "memory")

// ---------------- kernel 0: SSM discretization params -----------------------
__global__ void k_params(const float* __restrict__ log_dt,
                         const float* __restrict__ log_A_real,
                         const float* __restrict__ A_imag,
                         const float* __restrict__ B_re,
                         const float* __restrict__ B_im,
                         const float* __restrict__ C_re,
                         const float* __restrict__ C_im) {
    int i = blockIdx.x * blockDim.x + threadIdx.x;
    if (i >= HN) return;
    int h = i >> 5;
    float dt  = expf(log_dt[h]);
    float Ar  = -expf(log_A_real[i]);
    float Ai  = A_imag[i];
    float dtAr = dt * Ar, dtAi = dt * Ai;
    float denr = 1.f - 0.5f * dtAr;
    float deni = -0.5f * dtAi;
    float inv2 = 1.f / (denr * denr + deni * deni);
    float numr = 1.f + 0.5f * dtAr;
    float numi = 0.5f * dtAi;
    g_dAr[i] = (numr * denr + numi * deni) * inv2;
    g_dAi[i] = (numi * denr - numr * deni) * inv2;
    float sr =  dt * denr * inv2;
    float si = -dt * deni * inv2;
    float Br = B_re[i], Bi = B_im[i];
    #pragma unroll
    for (int c = 0; c < 2; c++) {
        float Cr = C_re[c * HN + i], Ci = C_im[c * HN + i];
        float cbr = Cr * Br - Ci * Bi;
        float cbi = Cr * Bi + Ci * Br;
        float er = 2.f * (cbr * sr - cbi * si);
        float ei = 2.f * (cbr * si + cbi * sr);
        if (c == 0) { g_c0r[i] = er; g_c0i[i] = ei; }
        else        { g_c1r[i] = er; g_c1i[i] = ei; }
    }
}

// ---------------- kernel 1: sequence lengths ---------------------------------
__global__ void k_len(const float* __restrict__ mask) {
    __shared__ float red[256];
    int b = blockIdx.x;
    float s = 0.f;
    for (int t = threadIdx.x; t < Ldim; t += 256) s += mask[b * Ldim + t];
    red[threadIdx.x] = s; __syncthreads();
    for (int o = 128; o; o >>= 1) {
        if (threadIdx.x < o) red[threadIdx.x] += red[threadIdx.x + o];
        __syncthreads();
    }
    if (threadIdx.x == 0) g_len[b] = red[0];
}

// ---------------- kernel 2: LayerNorm + mask + transpose -> (B,H,L) ----------
__global__ __launch_bounds__(256) void k_ln(const float* __restrict__ x,
                                            const float* __restrict__ gamma,
                                            const float* __restrict__ beta) {
    __shared__ float s[16][513];
    int b = blockIdx.y, t0 = blockIdx.x * 16;
    const float* xp = x + ((size_t)(b * Ldim + t0)) * Hdim;
    int tid = threadIdx.x;
    #pragma unroll
    for (int r = 0; r < 8; r++) {
        int id4 = tid + r * 256;
        int t = id4 >> 7, h4 = (id4 & 127) * 4;
        float4 v = ((const float4*)xp)[id4];
        s[t][h4] = v.x; s[t][h4+1] = v.y; s[t][h4+2] = v.z; s[t][h4+3] = v.w;
    }
    __syncthreads();
    int warp = tid >> 5, lane = tid & 31;
    float lenb = g_len[b];
    #pragma unroll
    for (int rr = 0; rr < 2; rr++) {
        int t = warp * 2 + rr;
        float sum = 0.f, sq = 0.f;
        float vals[16];
        #pragma unroll
        for (int k = 0; k < 16; k++) {
            float v = s[t][lane + 32 * k];
            vals[k] = v; sum += v; sq += v * v;
        }
        #pragma unroll
        for (int o = 16; o; o >>= 1) {
            sum += __shfl_xor_sync(0xffffffffu, sum, o);
            sq  += __shfl_xor_sync(0xffffffffu, sq,  o);
        }
        float mu = sum * (1.f / 512.f);
        float var = sq * (1.f / 512.f) - mu * mu;
        float rs = rsqrtf(var + 1e-5f);
        float mv = ((float)(t0 + t) < lenb) ? 1.f : 0.f;
        #pragma unroll
        for (int k = 0; k < 16; k++) {
            int h = lane + 32 * k;
            s[t][h] = (gamma[h] * (vals[k] - mu) * rs + beta[h]) * mv;
        }
    }
    __syncthreads();
    #pragma unroll
    for (int r = 0; r < 8; r++) {
        int id = tid + r * 256;            // 2048 float4 units
        int h = id >> 2, tq = (id & 3) * 4;
        float4 o;
        o.x = s[tq][h]; o.y = s[tq+1][h]; o.z = s[tq+2][h]; o.w = s[tq+3][h];
        *(float4*)(g_u + ((size_t)(b * Hdim + h)) * Ldim + t0 + tq) = o;
    }
}

// ---------------- kernel 3: bidirectional SSM scan (fwd/bwd concurrent) ------
__global__ __launch_bounds__(128, 7) void k_scan(const float* __restrict__ D) {
    int bid = blockIdx.x;
    int bwd = bid >= 512;
    int blk = bwd ? bid - 512 : bid;
    int tid  = threadIdx.x;
    int lane = tid & 31, warp = tid >> 5;
    int sub  = lane & 7;
    int idx  = blk * 16 + warp * 4 + (lane >> 3);   // = b*H + h
    int h    = idx & (Hdim - 1);
    const float* __restrict__ urow = g_u + (size_t)idx * Ldim;
    int pb = h * Ndim + sub * 4;

    float2 a01 = *(const float2*)&g_dAr[pb];
    float2 a23 = *(const float2*)&g_dAr[pb + 2];
    float2 i01 = *(const float2*)&g_dAi[pb];
    float2 i23 = *(const float2*)&g_dAi[pb + 2];
    u64 dAr0 = pk2f(a01.x, a01.y),  dAr1 = pk2f(a23.x, a23.y);
    u64 dAi0 = pk2f(i01.x, i01.y),  dAi1 = pk2f(i23.x, i23.y);
    u64 nAi0 = pk2f(-i01.x, -i01.y), nAi1 = pk2f(-i23.x, -i23.y);

    if (!bwd) {
        float* __restrict__ yrow = g_yf + (size_t)idx * Ldim;
        float Dh = D[h];
        float2 r01 = *(const float2*)&g_c0r[pb];
        float2 r23 = *(const float2*)&g_c0r[pb + 2];
        float2 q01 = *(const float2*)&g_c0i[pb];
        float2 q23 = *(const float2*)&g_c0i[pb + 2];
        u64 cr0 = pk2f(r01.x, r01.y),   cr1 = pk2f(r23.x, r23.y);
        u64 nci0 = pk2f(-q01.x, -q01.y), nci1 = pk2f(-q23.x, -q23.y);
        u64 s0r = 0, s0i = 0, s1r = 0, s1i = 0;
        float4 A0, A1, A2, A3; float2 umn;
        {
            const float4* u4 = (const float4*)urow;
            A0 = u4[0]; A1 = u4[1]; A2 = u4[2]; A3 = u4[3];
            umn = *(const float2*)(urow + sub * 2);
        }
        for (int t0 = 0; t0 < Ldim; t0 += 16) {
            float uu[16] = {A0.x,A0.y,A0.z,A0.w, A1.x,A1.y,A1.z,A1.w,
                            A2.x,A2.y,A2.z,A2.w, A3.x,A3.y,A3.z,A3.w};
            float2 um = umn;
            if (t0 + 16 < Ldim) {
                const float4* u4 = (const float4*)(urow + t0 + 16);
                A0 = u4[0]; A1 = u4[1]; A2 = u4[2]; A3 = u4[3];
                umn = *(const float2*)(urow + t0 + 16 + sub * 2);
            }
            float p[16];
            #pragma unroll
            for (int tt = 0; tt < 16; tt++) {
                u64 up = pk2f(uu[tt], uu[tt]);
                u64 x0 = fma2(nAi0, s0i, up);
                u64 m0 = mul2(dAi0, s0r);
                u64 x1 = fma2(nAi1, s1i, up);
                u64 m1 = mul2(dAi1, s1r);
                u64 nr0 = fma2(dAr0, s0r, x0);
                u64 ni0 = fma2(dAr0, s0i, m0);
                u64 nr1 = fma2(dAr1, s1r, x1);
                u64 ni1 = fma2(dAr1, s1i, m1);
                s0r = nr0; s0i = ni0; s1r = nr1; s1i = ni1;
                u64 acc = mul2(cr0, s0r);
                acc = fma2(nci0, s0i, acc);
                acc = fma2(cr1, s1r, acc);
                acc = fma2(nci1, s1i, acc);
                float2 aa = upk2(acc);
                p[tt] = aa.x + aa.y;
            }
            #pragma unroll
            for (int i = 0; i < 8; i++) {
                float send = (sub & 4) ? p[i] : p[i + 8];
                float r = __shfl_xor_sync(0xffffffffu, send, 4);
                p[i] = ((sub & 4) ? p[i + 8] : p[i]) + r;
            }
            #pragma unroll
            for (int i = 0; i < 4; i++) {
                float send = (sub & 2) ? p[i] : p[i + 4];
                float r = __shfl_xor_sync(0xffffffffu, send, 2);
                p[i] = ((sub & 2) ? p[i + 4] : p[i]) + r;
            }
            #pragma unroll
            for (int i = 0; i < 2; i++) {
                float send = (sub & 1) ? p[i] : p[i + 2];
                float r = __shfl_xor_sync(0xffffffffu, send, 1);
                p[i] = ((sub & 1) ? p[i + 2] : p[i]) + r;
            }
            float2 o;
            o.x = fmaf(Dh, um.x, p[0]);
            o.y = fmaf(Dh, um.y, p[1]);
            *(float2*)(yrow + t0 + sub * 2) = o;
        }
    } else {
        float* __restrict__ yrow = g_yb + (size_t)idx * Ldim;
        float2 r01 = *(const float2*)&g_c1r[pb];
        float2 r23 = *(const float2*)&g_c1r[pb + 2];
        float2 q01 = *(const float2*)&g_c1i[pb];
        float2 q23 = *(const float2*)&g_c1i[pb + 2];
        u64 cr0 = pk2f(r01.x, r01.y),   cr1 = pk2f(r23.x, r23.y);
        u64 nci0 = pk2f(-q01.x, -q01.y), nci1 = pk2f(-q23.x, -q23.y);
        u64 s0r = 0, s0i = 0, s1r = 0, s1i = 0;
        float4 A0, A1, A2, A3;
        {
            const float4* u4 = (const float4*)(urow + Ldim - 16);
            A0 = u4[0]; A1 = u4[1]; A2 = u4[2]; A3 = u4[3];
        }
        for (int t0 = Ldim - 16; t0 >= 0; t0 -= 16) {
            float uu[16] = {A0.x,A0.y,A0.z,A0.w, A1.x,A1.y,A1.z,A1.w,
                            A2.x,A2.y,A2.z,A2.w, A3.x,A3.y,A3.z,A3.w};
            if (t0 - 16 >= 0) {
                const float4* u4 = (const float4*)(urow + t0 - 16);
                A0 = u4[0]; A1 = u4[1]; A2 = u4[2]; A3 = u4[3];
            }
            float p[16];
            #pragma unroll
            for (int tt = 15; tt >= 0; tt--) {
                u64 acc = mul2(cr0, s0r);
                acc = fma2(nci0, s0i, acc);
                acc = fma2(cr1, s1r, acc);
                acc = fma2(nci1, s1i, acc);
                float2 aa = upk2(acc);
                p[tt] = aa.x + aa.y;
                u64 up = pk2f(uu[tt], uu[tt]);
                u64 x0 = fma2(nAi0, s0i, up);
                u64 m0 = mul2(dAi0, s0r);
                u64 x1 = fma2(nAi1, s1i, up);
                u64 m1 = mul2(dAi1, s1r);
                u64 nr0 = fma2(dAr0, s0r, x0);
                u64 ni0 = fma2(dAr0, s0i, m0);
                u64 nr1 = fma2(dAr1, s1r, x1);
                u64 ni1 = fma2(dAr1, s1i, m1);
                s0r = nr0; s0i = ni0; s1r = nr1; s1i = ni1;
            }
            #pragma unroll
            for (int i = 0; i < 8; i++) {
                float send = (sub & 4) ? p[i] : p[i + 8];
                float r = __shfl_xor_sync(0xffffffffu, send, 4);
                p[i] = ((sub & 4) ? p[i + 8] : p[i]) + r;
            }
            #pragma unroll
            for (int i = 0; i < 4; i++) {
                float send = (sub & 2) ? p[i] : p[i + 4];
                float r = __shfl_xor_sync(0xffffffffu, send, 2);
                p[i] = ((sub & 2) ? p[i + 4] : p[i]) + r;
            }
            #pragma unroll
            for (int i = 0; i < 2; i++) {
                float send = (sub & 1) ? p[i] : p[i + 2];
                float r = __shfl_xor_sync(0xffffffffu, send, 1);
                p[i] = ((sub & 1) ? p[i + 2] : p[i]) + r;
            }
            *(float2*)(yrow + t0 + sub * 2) = make_float2(p[0], p[1]);
        }
    }
}

// ---------------- kernel 3b: combine + GELU + bf16 hi/lo split + transpose ---
__global__ __launch_bounds__(256) void k_comb() {
    __shared__ float tile[64][33];
    int b = blockIdx.z, t0 = blockIdx.x * 32, h0 = blockIdx.y * 64;
    int tx = threadIdx.x, ty = threadIdx.y;
    #pragma unroll
    for (int r = 0; r < 8; r++) {
        int row = r * 8 + ty;
        size_t gi = ((size_t)(b * Hdim + h0 + row)) * Ldim + t0 + tx;
        tile[row][tx] = g_yf[gi] + g_yb[gi];
    }
    __syncthreads();
    int tid = ty * 32 + tx;
    int t = tid >> 3, hg = (tid & 7) * 8;
    __nv_bfloat16 hi8[8], lo8[8];
    #pragma unroll
    for (int j = 0; j < 8; j++) {
        float v = tile[hg + j][t];
        v = 0.5f * v * (1.f + erff(v * 0.70710678118654752f));
        __nv_bfloat16 hv = __float2bfloat16(v);
        hi8[j] = hv;
        lo8[j] = __float2bfloat16(v - __bfloat162float(hv));
    }
    size_t oi = ((size_t)(b * Ldim + t0 + t)) * Hdim + h0 + hg;
    *(uint4*)&g_yh[oi] = *(uint4*)hi8;
    *(uint4*)&g_yl[oi] = *(uint4*)lo8;
}

// ---------------- kernel 3c: W -> bf16 hi/lo ---------------------------------
__global__ void k_wsplit(const float* __restrict__ W) {
    int i = blockIdx.x * 256 + threadIdx.x;
    float w = W[i];
    __nv_bfloat16 hv = __float2bfloat16(w);
    g_wh[i] = hv;
    g_wl[i] = __float2bfloat16(w - __bfloat162float(hv));
}

// ---------------- kernel 4: WMMA bf16 split GEMM v3 (512 threads) ------------
// per CTA: M=128 (t), N=256 zc-cols (128 p + 128 q), K=512 in 32 chunks of 16.
// 16 warps: warp tile 32(M) x 64(N) -> acc[2][4] = 64 regs/thread, no spills.
// cp.async double-buffered; epilogue in two 64-row passes aliasing stage smem.
#define KC     16
#define LDS_AB 24                         // bf16 per smem row (16 + 8 pad)
#define A_MAT  (128 * LDS_AB * 2)         // 6144
#define B_MAT  (256 * LDS_AB * 2)         // 12288
#define STAGE_BYTES (2 * A_MAT + 2 * B_MAT)  // 36864
#define NCHUNK (Hdim / KC)                // 32
#define LDE  264                          // f32 epilogue row stride (256 + 8)
#define OFF_BIAS (2 * STAGE_BYTES)        // 73728
#define SMEM_TOT (OFF_BIAS + 1024)

__global__ __launch_bounds__(512, 1) void k_gemm(const float* __restrict__ bias,
                                                 const float* __restrict__ x,
                                                 float* __restrict__ out) {
    extern __shared__ char smem[];
    uint32_t sbase = smem_u32(smem);
    float* sepi  = (float*)smem;              // epilogue aliases stage buffers
    float* sbias = (float*)(smem + OFF_BIAS);

    int tid = threadIdx.x;
    int warp = tid >> 5;
    int by = blockIdx.y;
    int b = by >> 4, t0 = (by & 15) * 128;
    int n0 = blockIdx.x * 128;                // p-col base; q = 512 + same
    int wm = warp >> 2;                       // 0..3 -> rows wm*32
    int wn = warp & 3;                        // 0..3 -> cols wn*64 (of 256)

    if (tid < 128)       sbias[tid] = bias[n0 + tid];
    else if (tid < 256)  sbias[tid] = bias[512 + n0 + tid - 128];

    const __nv_bfloat16* Agh = g_yh + ((size_t)(b * Ldim + t0)) * Hdim;
    const __nv_bfloat16* Agl = g_yl + ((size_t)(b * Ldim + t0)) * Hdim;

    // staging: 1536 uint4 per chunk (Ah 256, Al 256, Bh 512, Bl 512); 3/thread
    auto stage = [&](int c, int buf) {
        int k0 = c * KC;
        uint32_t sb = sbase + buf * STAGE_BYTES;
        #pragma unroll
        for (int r = 0; r < 3; r++) {
            int id = tid + r * 512;
            const __nv_bfloat16* gp;
            uint32_t so;
            if (id < 512) {                   // A hi/lo: 256 uint4 each
                int m = id & 255;
                int row = m >> 1, j8 = (m & 1) * 8;
                const __nv_bfloat16* base = (id < 256) ? Agh : Agl;
                gp = base + (size_t)row * Hdim + k0 + j8;
                so = sb + (id < 256 ? 0 : A_MAT)
                        + (uint32_t)(row * LDS_AB + j8) * 2;
            } else {                          // B hi/lo: 512 uint4 each
                int m = (id - 512) & 511;
                int row = m >> 1, j8 = (m & 1) * 8;
                int wr = (row < 128) ? (n0 + row) : (512 + n0 + row - 128);
                const __nv_bfloat16* base = (id < 1024) ? g_wh : g_wl;
                gp = base + (size_t)wr * Hdim + k0 + j8;
                so = sb + 2 * A_MAT + (id < 1024 ? 0 : B_MAT)
                        + (uint32_t)(row * LDS_AB + j8) * 2;
            }
            cpa16(so, gp);
        }
        CPA_COMMIT();
    };

    wmma::fragment<wmma::accumulator, 16, 16, 16, float> acc[2][4];
    #pragma unroll
    for (int mi = 0; mi < 2; mi++)
        #pragma unroll
        for (int ni = 0; ni < 4; ni++) wmma::fill_fragment(acc[mi][ni], 0.f);

    stage(0, 0);
    for (int c = 0; c < NCHUNK; c++) {
        int buf = c & 1;
        if (c + 1 < NCHUNK) {
            stage(c + 1, buf ^ 1);
            CPA_WAIT(1);
        } else {
            CPA_WAIT(0);
        }
        __syncthreads();
        const __nv_bfloat16* sAh = (const __nv_bfloat16*)(smem + buf * STAGE_BYTES);
        const __nv_bfloat16* sAl = (const __nv_bfloat16*)((const char*)sAh + A_MAT);
        const __nv_bfloat16* sBh = (const __nv_bfloat16*)((const char*)sAh + 2 * A_MAT);
        const __nv_bfloat16* sBl = (const __nv_bfloat16*)((const char*)sBh + B_MAT);
        wmma::fragment<wmma::matrix_a, 16, 16, 16, __nv_bfloat16,
                       wmma::row_major> ah[2], al[2];
        #pragma unroll
        for (int mi = 0; mi < 2; mi++) {
            int mr = wm * 32 + mi * 16;
            wmma::load_matrix_sync(ah[mi], sAh + mr * LDS_AB, LDS_AB);
            wmma::load_matrix_sync(al[mi], sAl + mr * LDS_AB, LDS_AB);
        }
        #pragma unroll
        for (int ni = 0; ni < 4; ni++) {
            int nr = wn * 64 + ni * 16;
            wmma::fragment<wmma::matrix_b, 16, 16, 16, __nv_bfloat16,
                           wmma::col_major> bh, bl;
            wmma::load_matrix_sync(bh, sBh + nr * LDS_AB, LDS_AB);
            wmma::load_matrix_sync(bl, sBl + nr * LDS_AB, LDS_AB);
            #pragma unroll
            for (int mi = 0; mi < 2; mi++) {
                wmma::mma_sync(acc[mi][ni], ah[mi], bh, acc[mi][ni]);
                wmma::mma_sync(acc[mi][ni], ah[mi], bl, acc[mi][ni]);
                wmma::mma_sync(acc[mi][ni], al[mi], bh, acc[mi][ni]);
            }
        }
        __syncthreads();
    }

    // ---- epilogue: two 64-row passes; rows wm*32 -> pass = wm>>1 ------------
    #pragma unroll
    for (int pass = 0; pass < 2; pass++) {
        if ((wm >> 1) == pass) {
            int rbase = (wm & 1) * 32;       // row within 64-row pass tile
            #pragma unroll
            for (int mi = 0; mi < 2; mi++)
                #pragma unroll
                for (int ni = 0; ni < 4; ni++)
                    wmma::store_matrix_sync(sepi + (rbase + mi * 16) * LDE
                                                 + wn * 64 + ni * 16,
                                            acc[mi][ni], LDE, wmma::mem_row_major);
        }
        __syncthreads();
        {
            int r = tid >> 3, c0 = (tid & 7) * 16;   // 64 rows x 8 col-chunks
            size_t m = (size_t)b * Ldim + t0 + pass * 64 + r;
            size_t orow = m * Hdim + n0 + c0;
            const float* er = sepi + r * LDE + c0;
            const float* sbp = sbias + c0;
            #pragma unroll
            for (int j = 0; j < 16; j += 4) {
                float4 xv = *(const float4*)(x + orow + j);
                float4 o;
                float p0 = er[j]     + sbp[j];
                float p1 = er[j + 1] + sbp[j + 1];
                float p2 = er[j + 2] + sbp[j + 2];
                float p3 = er[j + 3] + sbp[j + 3];
                float q0 = er[128 + j]     + sbp[128 + j];
                float q1 = er[128 + j + 1] + sbp[128 + j + 1];
                float q2 = er[128 + j + 2] + sbp[128 + j + 2];
                float q3 = er[128 + j + 3] + sbp[128 + j + 3];
                o.x = p0 / (1.f + expf(-q0)) + xv.x;
                o.y = p1 / (1.f + expf(-q1)) + xv.y;
                o.z = p2 / (1.f + expf(-q2)) + xv.z;
                o.w = p3 / (1.f + expf(-q3)) + xv.w;
                *(float4*)(out + orow + j) = o;
            }
        }
        __syncthreads();
    }
}

// ---------------- launch -----------------------------------------------------
extern "C" void kernel_launch(void* const* d_in, const int* in_sizes, int n_in,
                              void* d_out, int out_size) {
    const float* x          = (const float*)d_in[0];
    const float* input_mask = (const float*)d_in[1];
    const float* log_dt     = (const float*)d_in[2];
    const float* log_A_real = (const float*)d_in[3];
    const float* A_imag     = (const float*)d_in[4];
    const float* B_re       = (const float*)d_in[5];
    const float* B_im       = (const float*)d_in[6];
    const float* C_re       = (const float*)d_in[7];
    const float* C_im       = (const float*)d_in[8];
    const float* Dv         = (const float*)d_in[9];
    const float* W_out      = (const float*)d_in[10];
    const float* b_out      = (const float*)d_in[11];
    const float* ln_gamma   = (const float*)d_in[12];
    const float* ln_beta    = (const float*)d_in[13];
    float* out = (float*)d_out;

    cudaFuncSetAttribute(k_gemm, cudaFuncAttributeMaxDynamicSharedMemorySize,
                         SMEM_TOT);

    k_params<<<(HN + 255) / 256, 256>>>(log_dt, log_A_real, A_imag,
                                        B_re, B_im, C_re, C_im);
    k_len<<<Bdim, 256>>>(input_mask);
    k_ln<<<dim3(Ldim / 16, Bdim), 256>>>(x, ln_gamma, ln_beta);
    k_scan<<<1024, 128>>>(Dv);
    k_wsplit<<<2 * Hdim * Hdim / 256, 256>>>(W_out);
    k_comb<<<dim3(Ldim / 32, Hdim / 64, Bdim), dim3(32, 8)>>>();
    k_gemm<<<dim3(Hdim / 128, Bdim * (Ldim / 128)), 512, SMEM_TOT>>>(b_out, x, out);
}

// round 17
// speedup vs baseline: 1.3668x; 1.3668x over previous
#include <cuda_runtime.h>
#include <cuda_fp16.h>
#include <mma.h>
#include <math.h>
#include <cstdint>

using namespace nvcuda;

#define Bdim 16
#define Ldim 2048
#define Hdim 512
#define Ndim 32
#define HN   (Hdim*Ndim)
#define BH   (Bdim*Hdim)
#define BHL  (Bdim*Hdim*Ldim)

typedef unsigned long long u64;

// ---------------- scratch (device globals; no allocation allowed) -----------
__device__ float g_u [BHL];                  // (B,H,L) masked+LN'd input
__device__ float g_yf[BHL];                  // (B,H,L) fwd conv + D*u
__device__ float g_yb[BHL];                  // (B,H,L) bwd conv
__device__ __half g_ya[BHL];                 // (B,L,H) fp16(gelu(y))
__device__ __half g_wh[2*Hdim*Hdim];         // W hi fp16 (1024,512) K-major
__device__ __half g_wl[2*Hdim*Hdim];         // W lo fp16
__device__ float g_dAr[HN], g_dAi[HN];
__device__ float g_c0r[HN], g_c0i[HN], g_c1r[HN], g_c1i[HN];
__device__ float g_len[Bdim];

// ---------------- packed f32x2 helpers (sm_100+) -----------------------------
__device__ __forceinline__ u64 pk2f(float a, float b) {
    u64 r; asm("mov.b64 %0,{%1,%2};" : "=l"(r) : "f"(a), "f"(b)); return r;
}
__device__ __forceinline__ u64 fma2(u64 a, u64 b, u64 c) {
    u64 d; asm("fma.rn.f32x2 %0,%1,%2,%3;" : "=l"(d) : "l"(a), "l"(b), "l"(c)); return d;
}
__device__ __forceinline__ u64 mul2(u64 a, u64 b) {
    u64 d; asm("mul.rn.f32x2 %0,%1,%2;" : "=l"(d) : "l"(a), "l"(b)); return d;
}
__device__ __forceinline__ float2 upk2(u64 v) {
    float2 f; asm("mov.b64 {%0,%1},%2;" : "=f"(f.x), "=f"(f.y) : "l"(v)); return f;
}

// ---------------- cp.async helpers -------------------------------------------
__device__ __forceinline__ uint32_t smem_u32(const void* p) {
    uint32_t a;
    asm("{ .reg .u64 t; cvta.to.shared.u64 t, %1; cvt.u32.u64 %0, t; }"
        : "=r"(a) : "l"(p));
    return a;
}
__device__ __forceinline__ void cpa16(uint32_t s, const void* g) {
    asm volatile("cp.async.cg.shared.global [%0], [%1], 16;" :: "r"(s), "l"(g));
}
#define CPA_COMMIT()  asm volatile("cp.async.commit_group;" ::: "memory")
#define CPA_WAIT(n)   asm volatile("cp.async.wait_group %0;" :: "n"(n) : "memory")

// ---------------- kernel 0: SSM discretization params -----------------------
__global__ void k_params(const float* __restrict__ log_dt,
                         const float* __restrict__ log_A_real,
                         const float* __restrict__ A_imag,
                         const float* __restrict__ B_re,
                         const float* __restrict__ B_im,
                         const float* __restrict__ C_re,
                         const float* __restrict__ C_im) {
    int i = blockIdx.x * blockDim.x + threadIdx.x;
    if (i >= HN) return;
    int h = i >> 5;
    float dt  = expf(log_dt[h]);
    float Ar  = -expf(log_A_real[i]);
    float Ai  = A_imag[i];
    float dtAr = dt * Ar, dtAi = dt * Ai;
    float denr = 1.f - 0.5f * dtAr;
    float deni = -0.5f * dtAi;
    float inv2 = 1.f / (denr * denr + deni * deni);
    float numr = 1.f + 0.5f * dtAr;
    float numi = 0.5f * dtAi;
    g_dAr[i] = (numr * denr + numi * deni) * inv2;
    g_dAi[i] = (numi * denr - numr * deni) * inv2;
    float sr =  dt * denr * inv2;
    float si = -dt * deni * inv2;
    float Br = B_re[i], Bi = B_im[i];
    #pragma unroll
    for (int c = 0; c < 2; c++) {
        float Cr = C_re[c * HN + i], Ci = C_im[c * HN + i];
        float cbr = Cr * Br - Ci * Bi;
        float cbi = Cr * Bi + Ci * Br;
        float er = 2.f * (cbr * sr - cbi * si);
        float ei = 2.f * (cbr * si + cbi * sr);
        if (c == 0) { g_c0r[i] = er; g_c0i[i] = ei; }
        else        { g_c1r[i] = er; g_c1i[i] = ei; }
    }
}

// ---------------- kernel 1: sequence lengths ---------------------------------
__global__ void k_len(const float* __restrict__ mask) {
    __shared__ float red[256];
    int b = blockIdx.x;
    float s = 0.f;
    for (int t = threadIdx.x; t < Ldim; t += 256) s += mask[b * Ldim + t];
    red[threadIdx.x] = s; __syncthreads();
    for (int o = 128; o; o >>= 1) {
        if (threadIdx.x < o) red[threadIdx.x] += red[threadIdx.x + o];
        __syncthreads();
    }
    if (threadIdx.x == 0) g_len[b] = red[0];
}

// ---------------- kernel 2: LayerNorm + mask + transpose -> (B,H,L) ----------
__global__ __launch_bounds__(256) void k_ln(const float* __restrict__ x,
                                            const float* __restrict__ gamma,
                                            const float* __restrict__ beta) {
    __shared__ float s[16][513];
    int b = blockIdx.y, t0 = blockIdx.x * 16;
    const float* xp = x + ((size_t)(b * Ldim + t0)) * Hdim;
    int tid = threadIdx.x;
    #pragma unroll
    for (int r = 0; r < 8; r++) {
        int id4 = tid + r * 256;
        int t = id4 >> 7, h4 = (id4 & 127) * 4;
        float4 v = ((const float4*)xp)[id4];
        s[t][h4] = v.x; s[t][h4+1] = v.y; s[t][h4+2] = v.z; s[t][h4+3] = v.w;
    }
    __syncthreads();
    int warp = tid >> 5, lane = tid & 31;
    float lenb = g_len[b];
    #pragma unroll
    for (int rr = 0; rr < 2; rr++) {
        int t = warp * 2 + rr;
        float sum = 0.f, sq = 0.f;
        float vals[16];
        #pragma unroll
        for (int k = 0; k < 16; k++) {
            float v = s[t][lane + 32 * k];
            vals[k] = v; sum += v; sq += v * v;
        }
        #pragma unroll
        for (int o = 16; o; o >>= 1) {
            sum += __shfl_xor_sync(0xffffffffu, sum, o);
            sq  += __shfl_xor_sync(0xffffffffu, sq,  o);
        }
        float mu = sum * (1.f / 512.f);
        float var = sq * (1.f / 512.f) - mu * mu;
        float rs = rsqrtf(var + 1e-5f);
        float mv = ((float)(t0 + t) < lenb) ? 1.f : 0.f;
        #pragma unroll
        for (int k = 0; k < 16; k++) {
            int h = lane + 32 * k;
            s[t][h] = (gamma[h] * (vals[k] - mu) * rs + beta[h]) * mv;
        }
    }
    __syncthreads();
    #pragma unroll
    for (int r = 0; r < 8; r++) {
        int id = tid + r * 256;            // 2048 float4 units
        int h = id >> 2, tq = (id & 3) * 4;
        float4 o;
        o.x = s[tq][h]; o.y = s[tq+1][h]; o.z = s[tq+2][h]; o.w = s[tq+3][h];
        *(float4*)(g_u + ((size_t)(b * Hdim + h)) * Ldim + t0 + tq) = o;
    }
}

// ---------------- kernel 3: bidirectional SSM scan (fwd/bwd concurrent) ------
__global__ __launch_bounds__(128, 7) void k_scan(const float* __restrict__ D) {
    int bid = blockIdx.x;
    int bwd = bid >= 512;
    int blk = bwd ? bid - 512 : bid;
    int tid  = threadIdx.x;
    int lane = tid & 31, warp = tid >> 5;
    int sub  = lane & 7;
    int idx  = blk * 16 + warp * 4 + (lane >> 3);   // = b*H + h
    int h    = idx & (Hdim - 1);
    const float* __restrict__ urow = g_u + (size_t)idx * Ldim;
    int pb = h * Ndim + sub * 4;

    float2 a01 = *(const float2*)&g_dAr[pb];
    float2 a23 = *(const float2*)&g_dAr[pb + 2];
    float2 i01 = *(const float2*)&g_dAi[pb];
    float2 i23 = *(const float2*)&g_dAi[pb + 2];
    u64 dAr0 = pk2f(a01.x, a01.y),  dAr1 = pk2f(a23.x, a23.y);
    u64 dAi0 = pk2f(i01.x, i01.y),  dAi1 = pk2f(i23.x, i23.y);
    u64 nAi0 = pk2f(-i01.x, -i01.y), nAi1 = pk2f(-i23.x, -i23.y);

    if (!bwd) {
        float* __restrict__ yrow = g_yf + (size_t)idx * Ldim;
        float Dh = D[h];
        float2 r01 = *(const float2*)&g_c0r[pb];
        float2 r23 = *(const float2*)&g_c0r[pb + 2];
        float2 q01 = *(const float2*)&g_c0i[pb];
        float2 q23 = *(const float2*)&g_c0i[pb + 2];
        u64 cr0 = pk2f(r01.x, r01.y),   cr1 = pk2f(r23.x, r23.y);
        u64 nci0 = pk2f(-q01.x, -q01.y), nci1 = pk2f(-q23.x, -q23.y);
        u64 s0r = 0, s0i = 0, s1r = 0, s1i = 0;
        float4 A0, A1, A2, A3; float2 umn;
        {
            const float4* u4 = (const float4*)urow;
            A0 = u4[0]; A1 = u4[1]; A2 = u4[2]; A3 = u4[3];
            umn = *(const float2*)(urow + sub * 2);
        }
        for (int t0 = 0; t0 < Ldim; t0 += 16) {
            float uu[16] = {A0.x,A0.y,A0.z,A0.w, A1.x,A1.y,A1.z,A1.w,
                            A2.x,A2.y,A2.z,A2.w, A3.x,A3.y,A3.z,A3.w};
            float2 um = umn;
            if (t0 + 16 < Ldim) {
                const float4* u4 = (const float4*)(urow + t0 + 16);
                A0 = u4[0]; A1 = u4[1]; A2 = u4[2]; A3 = u4[3];
                umn = *(const float2*)(urow + t0 + 16 + sub * 2);
            }
            float p[16];
            #pragma unroll
            for (int tt = 0; tt < 16; tt++) {
                u64 up = pk2f(uu[tt], uu[tt]);
                u64 x0 = fma2(nAi0, s0i, up);
                u64 m0 = mul2(dAi0, s0r);
                u64 x1 = fma2(nAi1, s1i, up);
                u64 m1 = mul2(dAi1, s1r);
                u64 nr0 = fma2(dAr0, s0r, x0);
                u64 ni0 = fma2(dAr0, s0i, m0);
                u64 nr1 = fma2(dAr1, s1r, x1);
                u64 ni1 = fma2(dAr1, s1i, m1);
                s0r = nr0; s0i = ni0; s1r = nr1; s1i = ni1;
                u64 acc = mul2(cr0, s0r);
                acc = fma2(nci0, s0i, acc);
                acc = fma2(cr1, s1r, acc);
                acc = fma2(nci1, s1i, acc);
                float2 aa = upk2(acc);
                p[tt] = aa.x + aa.y;
            }
            #pragma unroll
            for (int i = 0; i < 8; i++) {
                float send = (sub & 4) ? p[i] : p[i + 8];
                float r = __shfl_xor_sync(0xffffffffu, send, 4);
                p[i] = ((sub & 4) ? p[i + 8] : p[i]) + r;
            }
            #pragma unroll
            for (int i = 0; i < 4; i++) {
                float send = (sub & 2) ? p[i] : p[i + 4];
                float r = __shfl_xor_sync(0xffffffffu, send, 2);
                p[i] = ((sub & 2) ? p[i + 4] : p[i]) + r;
            }
            #pragma unroll
            for (int i = 0; i < 2; i++) {
                float send = (sub & 1) ? p[i] : p[i + 2];
                float r = __shfl_xor_sync(0xffffffffu, send, 1);
                p[i] = ((sub & 1) ? p[i + 2] : p[i]) + r;
            }
            float2 o;
            o.x = fmaf(Dh, um.x, p[0]);
            o.y = fmaf(Dh, um.y, p[1]);
            *(float2*)(yrow + t0 + sub * 2) = o;
        }
    } else {
        float* __restrict__ yrow = g_yb + (size_t)idx * Ldim;
        float2 r01 = *(const float2*)&g_c1r[pb];
        float2 r23 = *(const float2*)&g_c1r[pb + 2];
        float2 q01 = *(const float2*)&g_c1i[pb];
        float2 q23 = *(const float2*)&g_c1i[pb + 2];
        u64 cr0 = pk2f(r01.x, r01.y),   cr1 = pk2f(r23.x, r23.y);
        u64 nci0 = pk2f(-q01.x, -q01.y), nci1 = pk2f(-q23.x, -q23.y);
        u64 s0r = 0, s0i = 0, s1r = 0, s1i = 0;
        float4 A0, A1, A2, A3;
        {
            const float4* u4 = (const float4*)(urow + Ldim - 16);
            A0 = u4[0]; A1 = u4[1]; A2 = u4[2]; A3 = u4[3];
        }
        for (int t0 = Ldim - 16; t0 >= 0; t0 -= 16) {
            float uu[16] = {A0.x,A0.y,A0.z,A0.w, A1.x,A1.y,A1.z,A1.w,
                            A2.x,A2.y,A2.z,A2.w, A3.x,A3.y,A3.z,A3.w};
            if (t0 - 16 >= 0) {
                const float4* u4 = (const float4*)(urow + t0 - 16);
                A0 = u4[0]; A1 = u4[1]; A2 = u4[2]; A3 = u4[3];
            }
            float p[16];
            #pragma unroll
            for (int tt = 15; tt >= 0; tt--) {
                u64 acc = mul2(cr0, s0r);
                acc = fma2(nci0, s0i, acc);
                acc = fma2(cr1, s1r, acc);
                acc = fma2(nci1, s1i, acc);
                float2 aa = upk2(acc);
                p[tt] = aa.x + aa.y;
                u64 up = pk2f(uu[tt], uu[tt]);
                u64 x0 = fma2(nAi0, s0i, up);
                u64 m0 = mul2(dAi0, s0r);
                u64 x1 = fma2(nAi1, s1i, up);
                u64 m1 = mul2(dAi1, s1r);
                u64 nr0 = fma2(dAr0, s0r, x0);
                u64 ni0 = fma2(dAr0, s0i, m0);
                u64 nr1 = fma2(dAr1, s1r, x1);
                u64 ni1 = fma2(dAr1, s1i, m1);
                s0r = nr0; s0i = ni0; s1r = nr1; s1i = ni1;
            }
            #pragma unroll
            for (int i = 0; i < 8; i++) {
                float send = (sub & 4) ? p[i] : p[i + 8];
                float r = __shfl_xor_sync(0xffffffffu, send, 4);
                p[i] = ((sub & 4) ? p[i + 8] : p[i]) + r;
            }
            #pragma unroll
            for (int i = 0; i < 4; i++) {
                float send = (sub & 2) ? p[i] : p[i + 4];
                float r = __shfl_xor_sync(0xffffffffu, send, 2);
                p[i] = ((sub & 2) ? p[i + 4] : p[i]) + r;
            }
            #pragma unroll
            for (int i = 0; i < 2; i++) {
                float send = (sub & 1) ? p[i] : p[i + 2];
                float r = __shfl_xor_sync(0xffffffffu, send, 1);
                p[i] = ((sub & 1) ? p[i + 2] : p[i]) + r;
            }
            *(float2*)(yrow + t0 + sub * 2) = make_float2(p[0], p[1]);
        }
    }
}

// ---------------- kernel 3b: combine + GELU + fp16 convert + transpose -------
__global__ __launch_bounds__(256) void k_comb() {
    __shared__ float tile[64][33];
    int b = blockIdx.z, t0 = blockIdx.x * 32, h0 = blockIdx.y * 64;
    int tx = threadIdx.x, ty = threadIdx.y;
    #pragma unroll
    for (int r = 0; r < 8; r++) {
        int row = r * 8 + ty;
        size_t gi = ((size_t)(b * Hdim + h0 + row)) * Ldim + t0 + tx;
        tile[row][tx] = g_yf[gi] + g_yb[gi];
    }
    __syncthreads();
    int tid = ty * 32 + tx;
    int t = tid >> 3, hg = (tid & 7) * 8;
    __half a8[8];
    #pragma unroll
    for (int j = 0; j < 8; j++) {
        float v = tile[hg + j][t];
        v = 0.5f * v * (1.f + erff(v * 0.70710678118654752f));
        a8[j] = __float2half(v);
    }
    size_t oi = ((size_t)(b * Ldim + t0 + t)) * Hdim + h0 + hg;
    *(uint4*)&g_ya[oi] = *(uint4*)a8;
}

// ---------------- kernel 3c: W -> fp16 hi/lo ---------------------------------
__global__ void k_wsplit(const float* __restrict__ W) {
    int i = blockIdx.x * 256 + threadIdx.x;
    float w = W[i];
    __half hv = __float2half(w);
    g_wh[i] = hv;
    g_wl[i] = __float2half(w - __half2float(hv));
}

// ---------------- kernel 4: WMMA fp16 2-term GEMM, cp.async double-buffered --
// per CTA: M=128 (t), N=128 (64 p + 64 q cols), K=512 in 16 chunks of 32.
// acc += A*Bh + A*Bl  (fp32 accum; A single fp16, B split fp16 hi/lo)
#define KC     32
#define LDS_AB 40                         // fp16 elems per smem row (32+8 pad)
#define MAT_BYTES (128 * LDS_AB * 2)      // 10240
#define STAGE_BYTES (3 * MAT_BYTES)       // 30720 (A, Bh, Bl)
#define NCHUNK (Hdim / KC)                // 16
#define LDE  136
#define OFF_BIAS (128 * LDE * 4)          // 69632 (epilogue needs more than stage)
#define SMEM_TOT (OFF_BIAS + 512)

__global__ __launch_bounds__(256) void k_gemm(const float* __restrict__ bias,
                                              const float* __restrict__ x,
                                              float* __restrict__ out) {
    extern __shared__ char smem[];
    uint32_t sbase = smem_u32(smem);
    float* sepi  = (float*)smem;              // epilogue aliases stage buffers
    float* sbias = (float*)(smem + OFF_BIAS);

    int tid = threadIdx.x;
    int warp = tid >> 5;
    int by = blockIdx.y;
    int b = by >> 4, t0 = (by & 15) * 128;
    int n0 = blockIdx.x * 64;
    int wm = warp >> 2, wn = warp & 3;        // warp tile 64M x 32N

    if (tid < 64)       sbias[tid] = bias[n0 + tid];
    else if (tid < 128) sbias[tid] = bias[512 + n0 + tid - 64];

    const __half* Ag = g_ya + ((size_t)(b * Ldim + t0)) * Hdim;

    // staging: 1536 uint4 per chunk (A 512, Bh 512, Bl 512); 6 per thread
    auto stage = [&](int c, int buf) {
        int k0 = c * KC;
        uint32_t sb = sbase + buf * STAGE_BYTES;
        #pragma unroll
        for (int r = 0; r < 6; r++) {
            int id = tid + r * 256;
            int m = id & 511;
            int row = m >> 2, j8 = (m & 3) * 8;
            uint32_t off = (uint32_t)(row * LDS_AB + j8) * 2;
            const __half* gp;
            uint32_t so;
            if (id < 512) {                    // A
                gp = Ag + (size_t)row * Hdim + k0 + j8;
                so = sb + off;
            } else {                           // Bh / Bl
                int wr = (row < 64) ? (n0 + row) : (512 + n0 + row - 64);
                const __half* base = (id < 1024) ? g_wh : g_wl;
                gp = base + (size_t)wr * Hdim + k0 + j8;
                so = sb + (id < 1024 ? MAT_BYTES : 2 * MAT_BYTES) + off;
            }
            cpa16(so, gp);
        }
        CPA_COMMIT();
    };

    wmma::fragment<wmma::accumulator, 16, 16, 16, float> acc[4][2];
    #pragma unroll
    for (int mi = 0; mi < 4; mi++)
        #pragma unroll
        for (int ni = 0; ni < 2; ni++) wmma::fill_fragment(acc[mi][ni], 0.f);

    stage(0, 0);
    for (int c = 0; c < NCHUNK; c++) {
        int buf = c & 1;
        if (c + 1 < NCHUNK) {
            stage(c + 1, buf ^ 1);
            CPA_WAIT(1);
        } else {
            CPA_WAIT(0);
        }
        __syncthreads();
        const __half* sA  = (const __half*)(smem + buf * STAGE_BYTES);
        const __half* sBh = (const __half*)((const char*)sA + MAT_BYTES);
        const __half* sBl = (const __half*)((const char*)sA + 2 * MAT_BYTES);
        #pragma unroll
        for (int ks = 0; ks < KC / 16; ks++) {
            int kk = ks * 16;
            wmma::fragment<wmma::matrix_a, 16, 16, 16, __half,
                           wmma::row_major> af[4];
            #pragma unroll
            for (int mi = 0; mi < 4; mi++) {
                int mr = wm * 64 + mi * 16;
                wmma::load_matrix_sync(af[mi], sA + mr * LDS_AB + kk, LDS_AB);
            }
            #pragma unroll
            for (int ni = 0; ni < 2; ni++) {
                int nr = wn * 32 + ni * 16;
                wmma::fragment<wmma::matrix_b, 16, 16, 16, __half,
                               wmma::col_major> bh, bl;
                wmma::load_matrix_sync(bh, sBh + nr * LDS_AB + kk, LDS_AB);
                wmma::load_matrix_sync(bl, sBl + nr * LDS_AB + kk, LDS_AB);
                #pragma unroll
                for (int mi = 0; mi < 4; mi++) {
                    wmma::mma_sync(acc[mi][ni], af[mi], bh, acc[mi][ni]);
                    wmma::mma_sync(acc[mi][ni], af[mi], bl, acc[mi][ni]);
                }
            }
        }
        __syncthreads();
    }

    // ---- epilogue: dump accumulators to smem, fused bias+GLU+residual -------
    #pragma unroll
    for (int mi = 0; mi < 4; mi++)
        #pragma unroll
        for (int ni = 0; ni < 2; ni++)
            wmma::store_matrix_sync(sepi + (wm * 64 + mi * 16) * LDE
                                         + wn * 32 + ni * 16,
                                    acc[mi][ni], LDE, wmma::mem_row_major);
    __syncthreads();
    {
        int r = tid >> 1, cpart = (tid & 1) * 32;
        size_t orow = ((size_t)(b * Ldim + t0 + r)) * Hdim + n0 + cpart;
        const float* er = sepi + r * LDE;
        #pragma unroll
        for (int j = 0; j < 32; j += 4) {
            int cp = cpart + j;
            float4 xv = *(const float4*)(x + orow + j);
            float4 o;
            float p0 = er[cp]     + sbias[cp];
            float p1 = er[cp + 1] + sbias[cp + 1];
            float p2 = er[cp + 2] + sbias[cp + 2];
            float p3 = er[cp + 3] + sbias[cp + 3];
            float q0 = er[64 + cp]     + sbias[64 + cp];
            float q1 = er[64 + cp + 1] + sbias[64 + cp + 1];
            float q2 = er[64 + cp + 2] + sbias[64 + cp + 2];
            float q3 = er[64 + cp + 3] + sbias[64 + cp + 3];
            o.x = p0 / (1.f + expf(-q0)) + xv.x;
            o.y = p1 / (1.f + expf(-q1)) + xv.y;
            o.z = p2 / (1.f + expf(-q2)) + xv.z;
            o.w = p3 / (1.f + expf(-q3)) + xv.w;
            *(float4*)(out + orow + j) = o;
        }
    }
}

// ---------------- launch -----------------------------------------------------
extern "C" void kernel_launch(void* const* d_in, const int* in_sizes, int n_in,
                              void* d_out, int out_size) {
    const float* x          = (const float*)d_in[0];
    const float* input_mask = (const float*)d_in[1];
    const float* log_dt     = (const float*)d_in[2];
    const float* log_A_real = (const float*)d_in[3];
    const float* A_imag     = (const float*)d_in[4];
    const float* B_re       = (const float*)d_in[5];
    const float* B_im       = (const float*)d_in[6];
    const float* C_re       = (const float*)d_in[7];
    const float* C_im       = (const float*)d_in[8];
    const float* Dv         = (const float*)d_in[9];
    const float* W_out      = (const float*)d_in[10];
    const float* b_out      = (const float*)d_in[11];
    const float* ln_gamma   = (const float*)d_in[12];
    const float* ln_beta    = (const float*)d_in[13];
    float* out = (float*)d_out;

    cudaFuncSetAttribute(k_gemm, cudaFuncAttributeMaxDynamicSharedMemorySize,
                         SMEM_TOT);

    // order keeps k_scan in the launch slot ncu profiles
    k_params<<<(HN + 255) / 256, 256>>>(log_dt, log_A_real, A_imag,
                                        B_re, B_im, C_re, C_im);
    k_len<<<Bdim, 256>>>(input_mask);
    k_ln<<<dim3(Ldim / 16, Bdim), 256>>>(x, ln_gamma, ln_beta);
    k_scan<<<1024, 128>>>(Dv);
    k_wsplit<<<2 * Hdim * Hdim / 256, 256>>>(W_out);
    k_comb<<<dim3(Ldim / 32, Hdim / 64, Bdim), dim3(32, 8)>>>();
    k_gemm<<<dim3(Hdim / 64, Bdim * (Ldim / 128)), 256, SMEM_TOT>>>(b_out, x, out);
}